// round 9
// baseline (speedup 1.0000x reference)
#include <cuda_runtime.h>
#include <cuda_bf16.h>

// Focal BCE with logits, mean-reduced.
//   loss(x,t) = a * (1-q)^gamma * (-ln q),  q = sigmoid((t==1)? x : -x),
//               a = (t==1)? ALPHA : 1-ALPHA
// Base-2 formulation (ln2 folded into alpha):
//   u   = 2^(-log2e * y)             (= e^-y)
//   spl = log2(1 + u)                (= -ln(q)/ln2)
//   w   = 2^(-g*log2e*y - g*spl)     (= (1-q)^gamma)
//   loss = (a*ln2) * w * spl
//
// R8 (resubmitted R9; R8 bench was an infra failure, kernel never ran):
// R7's flat de-tailed schedule (HW work-distributor backfill instead of a
// static one-wave grid) with 4x larger CTA tiles to amortize CTA
// launch/drain churn and the per-CTA reduction epilogue (R7 ncu: occ-in-time
// 78.6%). Tile = 2048 float4 per CTA (8/thread, four pair-groups of 4
// front-batched LDG.E.128). Grid = n4/2048 = 5120 CTAs (~4.3 waves at 1184
// concurrent -> backfill granularity preserved).
//
// Epilogue (proven R5-R7): relaxed atomicAdd partials into g_sum;
// atom.acq_rel.inc counter (self-wraps at gridDim.x -> replay-deterministic);
// last block ld.acquire's g_sum, writes d_out, relaxed-resets g_sum.
// No gpu-scope fence (CCTL.IVALL L1-flush measured ~1us in R4).

#define FOCAL_GAMMA 0.2f
#define FOCAL_ALPHA 0.6f
#define LOG2E 1.4426950408889634f
#define LN2   0.6931471805599453f

#define TILE_F4   2048           // float4s per CTA
#define PAIRS     4              // pair-groups per thread

__device__ float        g_sum   = 0.0f;
__device__ unsigned int g_count = 0;

__device__ __forceinline__ float focal_elem(float x, int t) {
    bool pos = (t == 1);
    float y = pos ? x : -x;
    float a = pos ? (FOCAL_ALPHA * LN2) : ((1.0f - FOCAL_ALPHA) * LN2);
    float u   = exp2f(-LOG2E * y);                       // e^{-y}
    float spl = __log2f(1.0f + u);                       // -ln(q)/ln2
    float w   = exp2f(fmaf(-(FOCAL_GAMMA * LOG2E), y,
                           -FOCAL_GAMMA * spl));         // (1-q)^gamma
    return a * (w * spl);
}

__device__ __forceinline__ float focal_f4(float4 xv, int4 tv) {
    float s;
    s  = focal_elem(xv.x, tv.x);
    s += focal_elem(xv.y, tv.y);
    s += focal_elem(xv.z, tv.z);
    s += focal_elem(xv.w, tv.w);
    return s;
}

__global__ void __launch_bounds__(256)
focal_flat_kernel(const float4* __restrict__ x4,
                  const int4*  __restrict__ t4,
                  const float* __restrict__ x_scalar,
                  const int*   __restrict__ t_scalar,
                  float* __restrict__ out,
                  int n4, long long n_total, float inv_total) {
    int tid  = threadIdx.x;
    int base = blockIdx.x * TILE_F4 + tid;

    float acc = 0.0f;

    if (base + (TILE_F4 - 256) < n4) {
        // Full tile fast path: four pair-groups, each issuing 4 independent
        // LDG.E.128 before any consumption.
        #pragma unroll
        for (int k = 0; k < PAIRS; k++) {
            int i0 = base + (2 * k)     * 256;
            int i1 = base + (2 * k + 1) * 256;
            float4 xa = x4[i0];
            int4   ta = t4[i0];
            float4 xb = x4[i1];
            int4   tb = t4[i1];
            acc += focal_f4(xa, ta);
            acc += focal_f4(xb, tb);
        }
    } else {
        // Boundary tile: per-segment guards.
        #pragma unroll
        for (int k = 0; k < 2 * PAIRS; k++) {
            int i = base + k * 256;
            if (i < n4) {
                float4 xa = x4[i];
                int4   ta = t4[i];
                acc += focal_f4(xa, ta);
            }
        }
    }

    // Scalar tail (n_total % 4 != 0; empty for this shape). Block 0 only.
    if (blockIdx.x == 0) {
        long long tail_start = (long long)n4 * 4;
        for (long long j = tail_start + tid; j < n_total; j += 256) {
            acc += focal_elem(x_scalar[j], t_scalar[j]);
        }
    }

    // Intra-warp reduction
    #pragma unroll
    for (int off = 16; off > 0; off >>= 1)
        acc += __shfl_xor_sync(0xffffffffu, acc, off);

    __shared__ float warp_sums[8];
    int lane = tid & 31;
    int wid  = tid >> 5;
    if (lane == 0) warp_sums[wid] = acc;
    __syncthreads();

    if (wid == 0) {
        acc = (lane < 8) ? warp_sums[lane] : 0.0f;
        #pragma unroll
        for (int off = 4; off > 0; off >>= 1)
            acc += __shfl_xor_sync(0xffffffffu, acc, off);

        if (lane == 0) {
            atomicAdd(&g_sum, acc * inv_total);   // relaxed partial
            unsigned int prev;
            // acq_rel: releases our add before the inc, acquires all
            // prior blocks' adds when we observe the final count.
            asm volatile("atom.acq_rel.gpu.global.inc.u32 %0, [%1], %2;"
                         : "=r"(prev)
                         : "l"(&g_count), "r"(gridDim.x - 1)
                         : "memory");
            if (prev == gridDim.x - 1) {
                float total;
                asm volatile("ld.acquire.gpu.global.f32 %0, [%1];"
                             : "=f"(total) : "l"(&g_sum) : "memory");
                out[0] = total;
                asm volatile("st.relaxed.gpu.global.f32 [%0], %1;"
                             :: "l"(&g_sum), "f"(0.0f) : "memory");
            }
        }
    }
}

extern "C" void kernel_launch(void* const* d_in, const int* in_sizes, int n_in,
                              void* d_out, int out_size) {
    const float* logits = (const float*)d_in[0];
    const int*   target = (const int*)d_in[1];
    float* out = (float*)d_out;

    long long n_total = (long long)in_sizes[0];
    int n4 = (int)(n_total / 4);
    float inv_total = (float)(1.0 / (double)n_total);

    // One CTA per 2048 float4s (8 per thread). For N*C = 41.94M: 5120 CTAs.
    int blocks = (n4 + TILE_F4 - 1) / TILE_F4;
    if (blocks < 1) blocks = 1;

    focal_flat_kernel<<<blocks, 256>>>(
        (const float4*)logits, (const int4*)target,
        logits, target, out, n4, n_total, inv_total);
}

// round 12
// speedup vs baseline: 1.0282x; 1.0282x over previous
#include <cuda_runtime.h>
#include <cuda_bf16.h>

// Focal BCE with logits, mean-reduced.
//   loss(x,t) = a * (1-q)^gamma * (-ln q),  q = sigmoid((t==1)? x : -x),
//               a = (t==1)? ALPHA : 1-ALPHA
// Base-2 formulation (ln2 folded into alpha):
//   u   = 2^(-log2e * y)             (= e^-y)
//   spl = log2(1 + u)                (= -ln(q)/ln2)
//   w   = 2^(-g*log2e*y - g*spl)     (= (1-q)^gamma)
//   loss = (a*ln2) * w * spl
//
// R10 source, resubmitted (R10/R11 benches were broker infra failures; the
// kernel never ran either time). Tile-size bisection: measured 512 f4/CTA
// (20480 CTAs) = 53.34us; 2048 f4/CTA (5120 CTAs) = 54.88us (last-wave
// quantization: 4.3 waves -> ~35%-occupied final wave of ~4us CTAs).
// Midpoint: 1024 f4/CTA -> 10240 CTAs, ~8.65 waves, ~2us tail quantum
// (expected tail ~0.7us) with half of R7's epilogue count.
//
// Epilogue (proven R5-R9): relaxed atomicAdd partials into g_sum;
// atom.acq_rel.inc counter (self-wraps at gridDim.x -> replay-deterministic);
// last block ld.acquire's g_sum, writes d_out, relaxed-resets g_sum.
// No gpu-scope fence (CCTL.IVALL L1-flush measured ~1us in R4).

#define FOCAL_GAMMA 0.2f
#define FOCAL_ALPHA 0.6f
#define LOG2E 1.4426950408889634f
#define LN2   0.6931471805599453f

#define TILE_F4   1024           // float4s per CTA
#define PAIRS     2              // pair-groups per thread

__device__ float        g_sum   = 0.0f;
__device__ unsigned int g_count = 0;

__device__ __forceinline__ float focal_elem(float x, int t) {
    bool pos = (t == 1);
    float y = pos ? x : -x;
    float a = pos ? (FOCAL_ALPHA * LN2) : ((1.0f - FOCAL_ALPHA) * LN2);
    float u   = exp2f(-LOG2E * y);                       // e^{-y}
    float spl = __log2f(1.0f + u);                       // -ln(q)/ln2
    float w   = exp2f(fmaf(-(FOCAL_GAMMA * LOG2E), y,
                           -FOCAL_GAMMA * spl));         // (1-q)^gamma
    return a * (w * spl);
}

__device__ __forceinline__ float focal_f4(float4 xv, int4 tv) {
    float s;
    s  = focal_elem(xv.x, tv.x);
    s += focal_elem(xv.y, tv.y);
    s += focal_elem(xv.z, tv.z);
    s += focal_elem(xv.w, tv.w);
    return s;
}

__global__ void __launch_bounds__(256)
focal_flat_kernel(const float4* __restrict__ x4,
                  const int4*  __restrict__ t4,
                  const float* __restrict__ x_scalar,
                  const int*   __restrict__ t_scalar,
                  float* __restrict__ out,
                  int n4, long long n_total, float inv_total) {
    int tid  = threadIdx.x;
    int base = blockIdx.x * TILE_F4 + tid;

    float acc = 0.0f;

    if (base + (TILE_F4 - 256) < n4) {
        // Full tile fast path: two pair-groups, each issuing 4 independent
        // LDG.E.128 before any consumption.
        #pragma unroll
        for (int k = 0; k < PAIRS; k++) {
            int i0 = base + (2 * k)     * 256;
            int i1 = base + (2 * k + 1) * 256;
            float4 xa = x4[i0];
            int4   ta = t4[i0];
            float4 xb = x4[i1];
            int4   tb = t4[i1];
            acc += focal_f4(xa, ta);
            acc += focal_f4(xb, tb);
        }
    } else {
        // Boundary tile: per-segment guards.
        #pragma unroll
        for (int k = 0; k < 2 * PAIRS; k++) {
            int i = base + k * 256;
            if (i < n4) {
                float4 xa = x4[i];
                int4   ta = t4[i];
                acc += focal_f4(xa, ta);
            }
        }
    }

    // Scalar tail (n_total % 4 != 0; empty for this shape). Block 0 only.
    if (blockIdx.x == 0) {
        long long tail_start = (long long)n4 * 4;
        for (long long j = tail_start + tid; j < n_total; j += 256) {
            acc += focal_elem(x_scalar[j], t_scalar[j]);
        }
    }

    // Intra-warp reduction
    #pragma unroll
    for (int off = 16; off > 0; off >>= 1)
        acc += __shfl_xor_sync(0xffffffffu, acc, off);

    __shared__ float warp_sums[8];
    int lane = tid & 31;
    int wid  = tid >> 5;
    if (lane == 0) warp_sums[wid] = acc;
    __syncthreads();

    if (wid == 0) {
        acc = (lane < 8) ? warp_sums[lane] : 0.0f;
        #pragma unroll
        for (int off = 4; off > 0; off >>= 1)
            acc += __shfl_xor_sync(0xffffffffu, acc, off);

        if (lane == 0) {
            atomicAdd(&g_sum, acc * inv_total);   // relaxed partial
            unsigned int prev;
            // acq_rel: releases our add before the inc, acquires all
            // prior blocks' adds when we observe the final count.
            asm volatile("atom.acq_rel.gpu.global.inc.u32 %0, [%1], %2;"
                         : "=r"(prev)
                         : "l"(&g_count), "r"(gridDim.x - 1)
                         : "memory");
            if (prev == gridDim.x - 1) {
                float total;
                asm volatile("ld.acquire.gpu.global.f32 %0, [%1];"
                             : "=f"(total) : "l"(&g_sum) : "memory");
                out[0] = total;
                asm volatile("st.relaxed.gpu.global.f32 [%0], %1;"
                             :: "l"(&g_sum), "f"(0.0f) : "memory");
            }
        }
    }
}

extern "C" void kernel_launch(void* const* d_in, const int* in_sizes, int n_in,
                              void* d_out, int out_size) {
    const float* logits = (const float*)d_in[0];
    const int*   target = (const int*)d_in[1];
    float* out = (float*)d_out;

    long long n_total = (long long)in_sizes[0];
    int n4 = (int)(n_total / 4);
    float inv_total = (float)(1.0 / (double)n_total);

    // One CTA per 1024 float4s (4 per thread). For N*C = 41.94M: 10240 CTAs.
    int blocks = (n4 + TILE_F4 - 1) / TILE_F4;
    if (blocks < 1) blocks = 1;

    focal_flat_kernel<<<blocks, 256>>>(
        (const float4*)logits, (const int4*)target,
        logits, target, out, n4, n_total, inv_total);
}

// round 14
// speedup vs baseline: 1.0300x; 1.0018x over previous
#include <cuda_runtime.h>
#include <cuda_bf16.h>
#include <cstdint>

// Focal BCE with logits, mean-reduced.
//   loss(x,t) = a * (1-q)^gamma * (-ln q),  q = sigmoid((t==1)? x : -x),
//               a = (t==1)? ALPHA : 1-ALPHA
// Base-2 formulation (ln2 folded into alpha):
//   u   = 2^(-log2e * y)             (= e^-y)
//   spl = log2(1 + u)                (= -ln(q)/ln2)
//   w   = 2^(-g*log2e*y - g*spl)     (= (1-q)^gamma)
//   loss = (a*ln2) * w * spl
//
// R13 source, resubmitted (R13 bench was a broker infra failure; the kernel
// never compiled or ran). 256-bit loads (LDG.E.256, sm_100a) on the winning
// schedule. Measured plateau: 512 f4/CTA = 53.344us, 1024 = 53.376us (tie),
// 2048 = 54.88us (last-wave quantization). Keep 2048 elements/CTA
// (20480 CTAs, ~1us backfill quantum) but load with ld.global.nc.v8 ->
// each thread: one 32B logits load + one 32B target load instead of four
// 16B loads. Halves LDG count and L1tex wavefront-queue entries;
// bytes-in-flight unchanged (64B/thread).
//
// Epilogue (proven R5-R12): relaxed atomicAdd partials into g_sum;
// atom.acq_rel.inc counter (self-wraps at gridDim.x -> replay-deterministic);
// last block ld.acquire's g_sum, writes d_out, relaxed-resets g_sum.
// No gpu-scope fence (CCTL.IVALL L1-flush measured ~1us in R4).

#define FOCAL_GAMMA 0.2f
#define FOCAL_ALPHA 0.6f
#define LOG2E 1.4426950408889634f
#define LN2   0.6931471805599453f

#define TILE_ELEMS 2048          // elements per CTA (256 thr x 8)

__device__ float        g_sum   = 0.0f;
__device__ unsigned int g_count = 0;

__device__ __forceinline__ float focal_elem(float x, int t) {
    bool pos = (t == 1);
    float y = pos ? x : -x;
    float a = pos ? (FOCAL_ALPHA * LN2) : ((1.0f - FOCAL_ALPHA) * LN2);
    float u   = exp2f(-LOG2E * y);                       // e^{-y}
    float spl = __log2f(1.0f + u);                       // -ln(q)/ln2
    float w   = exp2f(fmaf(-(FOCAL_GAMMA * LOG2E), y,
                           -FOCAL_GAMMA * spl));         // (1-q)^gamma
    return a * (w * spl);
}

// 256-bit global loads (sm_100a). 32-byte aligned addresses required.
__device__ __forceinline__ void ldg256_f32(const float* p, float r[8]) {
    asm volatile("ld.global.nc.v8.f32 {%0,%1,%2,%3,%4,%5,%6,%7}, [%8];"
                 : "=f"(r[0]), "=f"(r[1]), "=f"(r[2]), "=f"(r[3]),
                   "=f"(r[4]), "=f"(r[5]), "=f"(r[6]), "=f"(r[7])
                 : "l"(p));
}

__device__ __forceinline__ void ldg256_s32(const int* p, int r[8]) {
    asm volatile("ld.global.nc.v8.b32 {%0,%1,%2,%3,%4,%5,%6,%7}, [%8];"
                 : "=r"(r[0]), "=r"(r[1]), "=r"(r[2]), "=r"(r[3]),
                   "=r"(r[4]), "=r"(r[5]), "=r"(r[6]), "=r"(r[7])
                 : "l"(p));
}

__global__ void __launch_bounds__(256)
focal_flat_kernel(const float* __restrict__ x,
                  const int*   __restrict__ t,
                  float* __restrict__ out,
                  long long n_total, float inv_total) {
    int tid = threadIdx.x;
    long long base = (long long)blockIdx.x * TILE_ELEMS + (long long)tid * 8;

    float acc = 0.0f;

    if (base + 8 <= n_total) {
        // Two independent LDG.E.256 issued back-to-back (64B in flight).
        float xv[8];
        int   tv[8];
        ldg256_f32(x + base, xv);
        ldg256_s32(t + base, tv);
        #pragma unroll
        for (int k = 0; k < 8; k++)
            acc += focal_elem(xv[k], tv[k]);
    } else {
        // Boundary chunk: scalar guarded loads.
        #pragma unroll
        for (int k = 0; k < 8; k++) {
            long long j = base + k;
            if (j < n_total)
                acc += focal_elem(x[j], t[j]);
        }
    }

    // Intra-warp reduction
    #pragma unroll
    for (int off = 16; off > 0; off >>= 1)
        acc += __shfl_xor_sync(0xffffffffu, acc, off);

    __shared__ float warp_sums[8];
    int lane = tid & 31;
    int wid  = tid >> 5;
    if (lane == 0) warp_sums[wid] = acc;
    __syncthreads();

    if (wid == 0) {
        acc = (lane < 8) ? warp_sums[lane] : 0.0f;
        #pragma unroll
        for (int off = 4; off > 0; off >>= 1)
            acc += __shfl_xor_sync(0xffffffffu, acc, off);

        if (lane == 0) {
            atomicAdd(&g_sum, acc * inv_total);   // relaxed partial
            unsigned int prev;
            // acq_rel: releases our add before the inc, acquires all
            // prior blocks' adds when we observe the final count.
            asm volatile("atom.acq_rel.gpu.global.inc.u32 %0, [%1], %2;"
                         : "=r"(prev)
                         : "l"(&g_count), "r"(gridDim.x - 1)
                         : "memory");
            if (prev == gridDim.x - 1) {
                float total;
                asm volatile("ld.acquire.gpu.global.f32 %0, [%1];"
                             : "=f"(total) : "l"(&g_sum) : "memory");
                out[0] = total;
                asm volatile("st.relaxed.gpu.global.f32 [%0], %1;"
                             :: "l"(&g_sum), "f"(0.0f) : "memory");
            }
        }
    }
}

extern "C" void kernel_launch(void* const* d_in, const int* in_sizes, int n_in,
                              void* d_out, int out_size) {
    const float* logits = (const float*)d_in[0];
    const int*   target = (const int*)d_in[1];
    float* out = (float*)d_out;

    long long n_total = (long long)in_sizes[0];
    float inv_total = (float)(1.0 / (double)n_total);

    // One CTA per 2048 elements (8 per thread). For N*C = 41.94M: 20480 CTAs.
    long long blocks_ll = (n_total + TILE_ELEMS - 1) / TILE_ELEMS;
    int blocks = (int)blocks_ll;
    if (blocks < 1) blocks = 1;

    focal_flat_kernel<<<blocks, 256>>>(logits, target, out,
                                       n_total, inv_total);
}